// round 2
// baseline (speedup 1.0000x reference)
#include <cuda_runtime.h>
#include <math.h>

#define T_TOK 3136
#define DIM   512
#define NH    8
#define HD    64
#define S_TOK 196
#define QT    56
#define NTILES (T_TOK / QT)   // 56

// Scratch (no allocations allowed)
__device__ float g_q[T_TOK * DIM];
__device__ float g_k[T_TOK * DIM];
__device__ float g_v[T_TOK * DIM];
__device__ float g_att[T_TOK * DIM];

// ---------------------------------------------------------------------------
// Tiled fp32 GEMM body: C[M=3136, N=512] = (A (+P)) @ W + bias
// 64x64 tile, 16x16 threads, 4x4 microtile, K-tile 16, padded smem stride 68
// ---------------------------------------------------------------------------
__device__ __forceinline__ void gemm_body(const float* __restrict__ A,
                                          const float* __restrict__ P,
                                          const float* __restrict__ W,
                                          const float* __restrict__ bias,
                                          float* __restrict__ Cout) {
    __shared__ float sA[16 * 68];   // [k][m], transposed A tile
    __shared__ float sB[16 * 68];   // [k][n]

    const int tx = threadIdx.x, ty = threadIdx.y;
    const int tid = ty * 16 + tx;
    const int m0 = blockIdx.y * 64;
    const int n0 = blockIdx.x * 64;

    float acc[4][4] = {};

    for (int k0 = 0; k0 < DIM; k0 += 16) {
#pragma unroll
        for (int it = 0; it < 4; it++) {
            int idx = tid + it * 256;           // 0..1023
            int r = idx >> 4, c = idx & 15;     // A tile: 64 rows x 16 k
            float av = A[(m0 + r) * DIM + k0 + c];
            if (P) av += P[(m0 + r) * DIM + k0 + c];
            sA[c * 68 + r] = av;
            int kr = idx >> 6, nc = idx & 63;   // W tile: 16 k x 64 n
            sB[kr * 68 + nc] = W[(k0 + kr) * DIM + n0 + nc];
        }
        __syncthreads();
#pragma unroll
        for (int kk = 0; kk < 16; kk++) {
            float4 a4 = *reinterpret_cast<const float4*>(&sA[kk * 68 + ty * 4]);
            float4 b4 = *reinterpret_cast<const float4*>(&sB[kk * 68 + tx * 4]);
            float a[4] = {a4.x, a4.y, a4.z, a4.w};
            float b[4] = {b4.x, b4.y, b4.z, b4.w};
#pragma unroll
            for (int i = 0; i < 4; i++)
#pragma unroll
                for (int j = 0; j < 4; j++)
                    acc[i][j] += a[i] * b[j];
        }
        __syncthreads();
    }
#pragma unroll
    for (int i = 0; i < 4; i++) {
        int m = m0 + ty * 4 + i;
#pragma unroll
        for (int j = 0; j < 4; j++) {
            int n = n0 + tx * 4 + j;
            Cout[m * DIM + n] = acc[i][j] + bias[n];
        }
    }
}

// Fused Q/K/V projection: blockIdx.z selects operand set
__global__ void proj_qkv(const float* __restrict__ xq, const float* __restrict__ xk,
                         const float* __restrict__ pos,
                         const float* __restrict__ Wq, const float* __restrict__ bq,
                         const float* __restrict__ Wk, const float* __restrict__ bk,
                         const float* __restrict__ Wv, const float* __restrict__ bv) {
    const float *A, *P, *W, *bias;
    float* out;
    if (blockIdx.z == 0)      { A = xq; P = pos;     W = Wq; bias = bq; out = g_q; }
    else if (blockIdx.z == 1) { A = xk; P = pos;     W = Wk; bias = bk; out = g_k; }
    else                      { A = xk; P = nullptr; W = Wv; bias = bv; out = g_v; }
    gemm_body(A, P, W, bias, out);
}

// Output projection straight into d_out
__global__ void proj_o(const float* __restrict__ Wo, const float* __restrict__ bo,
                       float* __restrict__ out) {
    gemm_body(g_att, nullptr, Wo, bo, out);
}

// ---------------------------------------------------------------------------
// Flash-style attention over 56-token tiles (tiles never straddle segments:
// all segment lengths are multiples of 56). grid = (56 qtiles, 8 heads).
// 224 active threads = 56 queries x 4 dim-groups of 16.
// ---------------------------------------------------------------------------
#define ATTN_SMEM_FLOATS (3 * QT * 68 + QT * 57 + 3 * QT + QT * 4)
#define ATTN_SMEM_BYTES  (ATTN_SMEM_FLOATS * 4)   // 60032

__global__ void attn_kernel(const int* __restrict__ channels) {
    extern __shared__ float smem[];
    float* sQ  = smem;               // QT x 68
    float* sK  = sQ + QT * 68;
    float* sV  = sK + QT * 68;
    float* sS  = sV + QT * 68;       // QT x 57
    float* sM  = sS + QT * 57;       // row max
    float* sL  = sM + QT;            // row sum
    float* sC  = sL + QT;            // correction factor
    float* sPS = sC + QT;            // QT x 4 partials

    const int tid = threadIdx.x;
    const int h = blockIdx.y;
    const int qbase = blockIdx.x * QT;

    // segment bounds for this query tile
    int off = 0, segs = 0, sege = 0;
#pragma unroll
    for (int i = 0; i < 4; i++) {
        int len = channels[i] * S_TOK;
        if (qbase >= off && qbase < off + len) { segs = off; sege = off + len; }
        off += len;
    }

    // Load Q tile (coalesced)
    for (int idx = tid; idx < QT * HD; idx += 256) {
        int r = idx >> 6, d = idx & 63;
        sQ[r * 68 + d] = g_q[(qbase + r) * DIM + h * HD + d];
    }

    const int q = tid >> 2, g = tid & 3;
    const bool active = tid < QT * 4;
    if (active && g == 0) { sM[q] = -INFINITY; sL[q] = 0.f; }

    float o[16];
#pragma unroll
    for (int i = 0; i < 16; i++) o[i] = 0.f;
    const float scale = 0.125f;   // 1/sqrt(64)

    for (int kb = segs; kb < sege; kb += QT) {
        __syncthreads();   // protects sK/sV/sS reuse + first-iter init
        for (int idx = tid; idx < QT * HD; idx += 256) {
            int r = idx >> 6, d = idx & 63;
            sK[r * 68 + d] = g_k[(kb + r) * DIM + h * HD + d];
            sV[r * 68 + d] = g_v[(kb + r) * DIM + h * HD + d];
        }
        __syncthreads();

        // scores: each active thread computes 14 dots of length 64
        if (active) {
            float accs[14];
#pragma unroll
            for (int jj = 0; jj < 14; jj++) accs[jj] = 0.f;
#pragma unroll
            for (int dc = 0; dc < 4; dc++) {
                float4 q0 = *reinterpret_cast<const float4*>(&sQ[q * 68 + dc * 16 + 0]);
                float4 q1 = *reinterpret_cast<const float4*>(&sQ[q * 68 + dc * 16 + 4]);
                float4 q2 = *reinterpret_cast<const float4*>(&sQ[q * 68 + dc * 16 + 8]);
                float4 q3 = *reinterpret_cast<const float4*>(&sQ[q * 68 + dc * 16 + 12]);
#pragma unroll
                for (int jj = 0; jj < 14; jj++) {
                    int j = g * 14 + jj;
                    const float* kr = &sK[j * 68 + dc * 16];
                    float4 k0 = *reinterpret_cast<const float4*>(kr + 0);
                    float4 k1 = *reinterpret_cast<const float4*>(kr + 4);
                    float4 k2 = *reinterpret_cast<const float4*>(kr + 8);
                    float4 k3 = *reinterpret_cast<const float4*>(kr + 12);
                    float s = q0.x*k0.x + q0.y*k0.y + q0.z*k0.z + q0.w*k0.w
                            + q1.x*k1.x + q1.y*k1.y + q1.z*k1.z + q1.w*k1.w
                            + q2.x*k2.x + q2.y*k2.y + q2.z*k2.z + q2.w*k2.w
                            + q3.x*k3.x + q3.y*k3.y + q3.z*k3.z + q3.w*k3.w;
                    accs[jj] += s;
                }
            }
            float lmax = -INFINITY;
#pragma unroll
            for (int jj = 0; jj < 14; jj++) {
                float s = accs[jj] * scale;
                sS[q * 57 + g * 14 + jj] = s;
                lmax = fmaxf(lmax, s);
            }
            sPS[q * 4 + g] = lmax;
        }
        __syncthreads();

        // new running max + correction
        if (active && g == 0) {
            float mt = fmaxf(fmaxf(sPS[q*4], sPS[q*4+1]), fmaxf(sPS[q*4+2], sPS[q*4+3]));
            float mnew = fmaxf(sM[q], mt);
            sC[q] = __expf(sM[q] - mnew);
            sM[q] = mnew;
        }
        __syncthreads();

        // exponentiate, partial sums, rescale accumulators
        if (active) {
            float mnew = sM[q];
            float psum = 0.f;
#pragma unroll
            for (int jj = 0; jj < 14; jj++) {
                int j = g * 14 + jj;
                float p = __expf(sS[q * 57 + j] - mnew);
                sS[q * 57 + j] = p;
                psum += p;
            }
            sPS[q * 4 + g] = psum;
            float corr = sC[q];
#pragma unroll
            for (int i = 0; i < 16; i++) o[i] *= corr;
        }
        __syncthreads();

        // accumulate P @ V; g==0 updates row sums concurrently
        if (active) {
            if (g == 0)
                sL[q] = sL[q] * sC[q] + sPS[q*4] + sPS[q*4+1] + sPS[q*4+2] + sPS[q*4+3];
            const int go = g * 16;
#pragma unroll 4
            for (int j = 0; j < QT; j++) {
                float p = sS[q * 57 + j];
                const float* vr = &sV[j * 68 + go];
                float4 v0 = *reinterpret_cast<const float4*>(vr + 0);
                float4 v1 = *reinterpret_cast<const float4*>(vr + 4);
                float4 v2 = *reinterpret_cast<const float4*>(vr + 8);
                float4 v3 = *reinterpret_cast<const float4*>(vr + 12);
                o[0]  += p * v0.x; o[1]  += p * v0.y; o[2]  += p * v0.z; o[3]  += p * v0.w;
                o[4]  += p * v1.x; o[5]  += p * v1.y; o[6]  += p * v1.z; o[7]  += p * v1.w;
                o[8]  += p * v2.x; o[9]  += p * v2.y; o[10] += p * v2.z; o[11] += p * v2.w;
                o[12] += p * v3.x; o[13] += p * v3.y; o[14] += p * v3.z; o[15] += p * v3.w;
            }
        }
    }
    __syncthreads();
    if (active) {
        float inv = 1.f / sL[q];
        const int go = g * 16;
        float* dst = &g_att[(qbase + q) * DIM + h * HD + go];
#pragma unroll
        for (int i = 0; i < 16; i++) dst[i] = o[i] * inv;
    }
}

// ---------------------------------------------------------------------------
extern "C" void kernel_launch(void* const* d_in, const int* in_sizes, int n_in,
                              void* d_out, int out_size) {
    const float* xq  = (const float*)d_in[0];
    const float* xk  = (const float*)d_in[1];
    const float* pos = (const float*)d_in[2];
    const int*   channels = (const int*)d_in[3];
    const float* Wq = (const float*)d_in[4];  const float* bq = (const float*)d_in[5];
    const float* Wk = (const float*)d_in[6];  const float* bk = (const float*)d_in[7];
    const float* Wv = (const float*)d_in[8];  const float* bv = (const float*)d_in[9];
    const float* Wo = (const float*)d_in[10]; const float* bo = (const float*)d_in[11];

    cudaFuncSetAttribute(attn_kernel, cudaFuncAttributeMaxDynamicSharedMemorySize,
                         ATTN_SMEM_BYTES);

    dim3 blk(16, 16);
    proj_qkv<<<dim3(8, 49, 3), blk>>>(xq, xk, pos, Wq, bq, Wk, bk, Wv, bv);
    attn_kernel<<<dim3(NTILES, NH), 256, ATTN_SMEM_BYTES>>>(channels);
    proj_o<<<dim3(8, 49, 1), blk>>>(Wo, bo, (float*)d_out);
}

// round 6
// speedup vs baseline: 1.4100x; 1.4100x over previous
#include <cuda_runtime.h>
#include <math.h>

#define T_TOK 3136
#define DIM   512
#define NH    8
#define HD    64
#define S_TOK 196
#define QT    56
#define KT    64
#define NTILES (T_TOK / QT)   // 56

// Scratch (no allocations allowed)
__device__ float g_q[T_TOK * DIM];
__device__ float g_k[T_TOK * DIM];
__device__ float g_v[T_TOK * DIM];
__device__ float g_att[T_TOK * DIM];

// ---------------------------------------------------------------------------
// Tiled fp32 GEMM body: C[M=3136, N=512] = (A (+P)) @ W + bias
// (at the 3-reg-FFMA SASS floor per R2 ncu; unchanged)
// ---------------------------------------------------------------------------
__device__ __forceinline__ void gemm_body(const float* __restrict__ A,
                                          const float* __restrict__ P,
                                          const float* __restrict__ W,
                                          const float* __restrict__ bias,
                                          float* __restrict__ Cout) {
    __shared__ float sA[16 * 68];   // [k][m], transposed A tile
    __shared__ float sB[16 * 68];   // [k][n]

    const int tx = threadIdx.x, ty = threadIdx.y;
    const int tid = ty * 16 + tx;
    const int m0 = blockIdx.y * 64;
    const int n0 = blockIdx.x * 64;

    float acc[4][4] = {};

    for (int k0 = 0; k0 < DIM; k0 += 16) {
#pragma unroll
        for (int it = 0; it < 4; it++) {
            int idx = tid + it * 256;           // 0..1023
            int r = idx >> 4, c = idx & 15;     // A tile: 64 rows x 16 k
            float av = A[(m0 + r) * DIM + k0 + c];
            if (P) av += P[(m0 + r) * DIM + k0 + c];
            sA[c * 68 + r] = av;
            int kr = idx >> 6, nc = idx & 63;   // W tile: 16 k x 64 n
            sB[kr * 68 + nc] = W[(k0 + kr) * DIM + n0 + nc];
        }
        __syncthreads();
#pragma unroll
        for (int kk = 0; kk < 16; kk++) {
            float4 a4 = *reinterpret_cast<const float4*>(&sA[kk * 68 + ty * 4]);
            float4 b4 = *reinterpret_cast<const float4*>(&sB[kk * 68 + tx * 4]);
            float a[4] = {a4.x, a4.y, a4.z, a4.w};
            float b[4] = {b4.x, b4.y, b4.z, b4.w};
#pragma unroll
            for (int i = 0; i < 4; i++)
#pragma unroll
                for (int j = 0; j < 4; j++)
                    acc[i][j] += a[i] * b[j];
        }
        __syncthreads();
    }
#pragma unroll
    for (int i = 0; i < 4; i++) {
        int m = m0 + ty * 4 + i;
#pragma unroll
        for (int j = 0; j < 4; j++) {
            int n = n0 + tx * 4 + j;
            Cout[m * DIM + n] = acc[i][j] + bias[n];
        }
    }
}

__global__ void proj_qkv(const float* __restrict__ xq, const float* __restrict__ xk,
                         const float* __restrict__ pos,
                         const float* __restrict__ Wq, const float* __restrict__ bq,
                         const float* __restrict__ Wk, const float* __restrict__ bk,
                         const float* __restrict__ Wv, const float* __restrict__ bv) {
    const float *A, *P, *W, *bias;
    float* out;
    if (blockIdx.z == 0)      { A = xq; P = pos;     W = Wq; bias = bq; out = g_q; }
    else if (blockIdx.z == 1) { A = xk; P = pos;     W = Wk; bias = bk; out = g_k; }
    else                      { A = xk; P = nullptr; W = Wv; bias = bv; out = g_v; }
    gemm_body(A, P, W, bias, out);
}

__global__ void proj_o(const float* __restrict__ Wo, const float* __restrict__ bo,
                       float* __restrict__ out) {
    gemm_body(g_att, nullptr, Wo, bo, out);
}

// ---------------------------------------------------------------------------
// Attention v2b: register-tiled flash attention.
// One block per (56-query tile, head). 256 threads; 14x16 grid of 4x4
// microtiles (224 active = 7 full warps).
// Smem strides are multiples of 4 floats (16B) so LDS.128 is legal:
//   Q^T stride 60, K^T stride 68, V stride 68, P stride 68.
// The a4 read is a 16-lane broadcast (1 address/ty-group); b4/v4 reads are
// row-contiguous across tx — both conflict-free independent of stride parity.
// ---------------------------------------------------------------------------
#define SQT_STRIDE 60
#define SKT_STRIDE 68
#define A2_SQT (HD * SQT_STRIDE)  // Q^T  [d][q]
#define A2_SKT (HD * SKT_STRIDE)  // K^T  [d][k]
#define A2_SV  (KT * 68)          // V    [k][d]
#define A2_SP  (QT * 68)          // P    [q][k]
#define A2_SMEM_FLOATS (A2_SQT + A2_SKT + A2_SV + A2_SP)
#define A2_SMEM_BYTES  (A2_SMEM_FLOATS * 4)   // 65408

__global__ void attn2(const int* __restrict__ channels) {
    extern __shared__ float sm[];
    float* sQt = sm;                 // [64][60]   (56 q cols used)
    float* sKt = sQt + A2_SQT;       // [64][68]
    float* sV  = sKt + A2_SKT;       // [64][68]
    float* sP  = sV  + A2_SV;        // [56][68]

    const int tid = threadIdx.x;
    const int tx = tid & 15;         // 16 col-groups (keys / head-dims)
    const int ty = tid >> 4;         // 16 row-groups, 14 active
    const int h = blockIdx.y;
    const int qbase = blockIdx.x * QT;
    const bool active = (ty < 14);

    // segment bounds for this query tile
    int off = 0, segs = 0, sege = 0;
#pragma unroll
    for (int i = 0; i < 4; i++) {
        int len = channels[i] * S_TOK;
        if (qbase >= off && qbase < off + len) { segs = off; sege = off + len; }
        off += len;
    }

    // Load Q transposed (coalesced GMEM read)
    for (int idx = tid; idx < QT * HD; idx += 256) {
        int r = idx >> 6, d = idx & 63;
        sQt[d * SQT_STRIDE + r] = g_q[(qbase + r) * DIM + h * HD + d];
    }

    float m[4], l[4], o[4][4];
#pragma unroll
    for (int i = 0; i < 4; i++) {
        m[i] = -INFINITY; l[i] = 0.f;
#pragma unroll
        for (int j = 0; j < 4; j++) o[i][j] = 0.f;
    }

    const float scale = 0.125f;   // 1/sqrt(64)

    for (int kb = segs; kb < sege; kb += KT) {
        int valid = sege - kb; if (valid > KT) valid = KT;

        __syncthreads();   // prev PV done before overwriting K/V
        for (int idx = tid; idx < KT * HD; idx += 256) {
            int r = idx >> 6, d = idx & 63;
            float kv = 0.f, vv = 0.f;
            if (r < valid) {
                int base = (kb + r) * DIM + h * HD + d;
                kv = g_k[base];
                vv = g_v[base];
            }
            sKt[d * SKT_STRIDE + r] = kv;
            sV [r * 68 + d] = vv;
        }
        __syncthreads();

        if (active) {
            // ---- S = Q K^T (4x4 microtile) ----
            float s[4][4];
#pragma unroll
            for (int i = 0; i < 4; i++)
#pragma unroll
                for (int j = 0; j < 4; j++) s[i][j] = 0.f;

            const float* qp = sQt + 4 * ty;
            const float* kp = sKt + 4 * tx;
#pragma unroll 8
            for (int d = 0; d < HD; d++) {
                float4 a4 = *reinterpret_cast<const float4*>(qp + d * SQT_STRIDE);
                float4 b4 = *reinterpret_cast<const float4*>(kp + d * SKT_STRIDE);
                float a[4] = {a4.x, a4.y, a4.z, a4.w};
                float b[4] = {b4.x, b4.y, b4.z, b4.w};
#pragma unroll
                for (int i = 0; i < 4; i++)
#pragma unroll
                    for (int j = 0; j < 4; j++)
                        s[i][j] += a[i] * b[j];
            }

            // scale + key tail mask
#pragma unroll
            for (int i = 0; i < 4; i++)
#pragma unroll
                for (int j = 0; j < 4; j++) {
                    s[i][j] *= scale;
                    if (4 * tx + j >= valid) s[i][j] = -1e30f;
                }

            // ---- online softmax, all in registers ----
#pragma unroll
            for (int i = 0; i < 4; i++) {
                float v = fmaxf(fmaxf(s[i][0], s[i][1]), fmaxf(s[i][2], s[i][3]));
#pragma unroll
                for (int w = 1; w < 16; w <<= 1)
                    v = fmaxf(v, __shfl_xor_sync(0xFFFFFFFFu, v, w));
                float mnew = fmaxf(m[i], v);
                float corr = __expf(m[i] - mnew);
                m[i] = mnew;
                float ps = 0.f;
#pragma unroll
                for (int j = 0; j < 4; j++) {
                    float p = __expf(s[i][j] - mnew);
                    s[i][j] = p;
                    ps += p;
                }
#pragma unroll
                for (int w = 1; w < 16; w <<= 1)
                    ps += __shfl_xor_sync(0xFFFFFFFFu, ps, w);
                l[i] = l[i] * corr + ps;
#pragma unroll
                for (int j = 0; j < 4; j++) o[i][j] *= corr;
            }

            // spill P (needed cross-thread in PV)
#pragma unroll
            for (int i = 0; i < 4; i++) {
                float4 p4 = make_float4(s[i][0], s[i][1], s[i][2], s[i][3]);
                *reinterpret_cast<float4*>(&sP[(4 * ty + i) * 68 + 4 * tx]) = p4;
            }
        }
        __syncthreads();   // P visible to all tx groups

        if (active) {
            // ---- O += P V (4x4 microtile over 64 keys) ----
            const float* vp = sV + 4 * tx;
            const float* pp = sP + (4 * ty) * 68;
#pragma unroll 4
            for (int j = 0; j < KT; j++) {
                float4 v4 = *reinterpret_cast<const float4*>(vp + j * 68);
                float p0 = pp[j];
                float p1 = pp[68 + j];
                float p2 = pp[136 + j];
                float p3 = pp[204 + j];
                o[0][0] += p0 * v4.x; o[0][1] += p0 * v4.y; o[0][2] += p0 * v4.z; o[0][3] += p0 * v4.w;
                o[1][0] += p1 * v4.x; o[1][1] += p1 * v4.y; o[1][2] += p1 * v4.z; o[1][3] += p1 * v4.w;
                o[2][0] += p2 * v4.x; o[2][1] += p2 * v4.y; o[2][2] += p2 * v4.z; o[2][3] += p2 * v4.w;
                o[3][0] += p3 * v4.x; o[3][1] += p3 * v4.y; o[3][2] += p3 * v4.z; o[3][3] += p3 * v4.w;
            }
        }
    }

    if (active) {
#pragma unroll
        for (int i = 0; i < 4; i++) {
            float inv = 1.f / l[i];
            float4 r4 = make_float4(o[i][0] * inv, o[i][1] * inv,
                                    o[i][2] * inv, o[i][3] * inv);
            *reinterpret_cast<float4*>(
                &g_att[(qbase + 4 * ty + i) * DIM + h * HD + 4 * tx]) = r4;
        }
    }
}

// ---------------------------------------------------------------------------
extern "C" void kernel_launch(void* const* d_in, const int* in_sizes, int n_in,
                              void* d_out, int out_size) {
    const float* xq  = (const float*)d_in[0];
    const float* xk  = (const float*)d_in[1];
    const float* pos = (const float*)d_in[2];
    const int*   channels = (const int*)d_in[3];
    const float* Wq = (const float*)d_in[4];  const float* bq = (const float*)d_in[5];
    const float* Wk = (const float*)d_in[6];  const float* bk = (const float*)d_in[7];
    const float* Wv = (const float*)d_in[8];  const float* bv = (const float*)d_in[9];
    const float* Wo = (const float*)d_in[10]; const float* bo = (const float*)d_in[11];

    cudaFuncSetAttribute(attn2, cudaFuncAttributeMaxDynamicSharedMemorySize,
                         A2_SMEM_BYTES);

    dim3 blk(16, 16);
    proj_qkv<<<dim3(8, 49, 3), blk>>>(xq, xk, pos, Wq, bq, Wk, bk, Wv, bv);
    attn2<<<dim3(NTILES, NH), 256, A2_SMEM_BYTES>>>(channels);
    proj_o<<<dim3(8, 49, 1), blk>>>(Wo, bo, (float*)d_out);
}

// round 8
// speedup vs baseline: 2.9986x; 2.1267x over previous
#include <cuda_runtime.h>
#include <math.h>
#include <stdint.h>

#define T_TOK 3136
#define DIM   512
#define NH    8
#define HD    64
#define S_TOK 196
#define QT    56
#define KT    64
#define NTILES (T_TOK / QT)   // 56

// Scratch (no allocations allowed)
__device__ float g_q[T_TOK * DIM];
__device__ float g_k[T_TOK * DIM];
__device__ float g_v[T_TOK * DIM];
__device__ float g_att[T_TOK * DIM];

// ---------------------------------------------------------------------------
// TF32 tensor-core GEMM: C[3136,512] = (A (+P)) @ W + bias
// BM=64, BN=64, BK=16. 256 threads = 8 warps, warp grid 2(M)x4(N),
// warp tile 32x16 -> 2x2 mma(16x8) tiles. Double-buffered smem.
// sA stride 20 (frag reads hit all 32 banks), sB stride 72 (8k+n distinct).
// ---------------------------------------------------------------------------
#define BM 64
#define BN 64
#define BK 16
#define SA_STR 20
#define SB_STR 72

__device__ __forceinline__ float to_tf32(float x) {
    uint32_t u;
    asm("cvt.rna.tf32.f32 %0, %1;" : "=r"(u) : "f"(x));
    return __uint_as_float(u);
}

__device__ __forceinline__ void mma_tf32(float* d, const uint32_t* a,
                                         uint32_t b0, uint32_t b1) {
    asm volatile(
        "mma.sync.aligned.m16n8k8.row.col.f32.tf32.tf32.f32 "
        "{%0,%1,%2,%3}, {%4,%5,%6,%7}, {%8,%9}, {%0,%1,%2,%3};\n"
        : "+f"(d[0]), "+f"(d[1]), "+f"(d[2]), "+f"(d[3])
        : "r"(a[0]), "r"(a[1]), "r"(a[2]), "r"(a[3]), "r"(b0), "r"(b1));
}

__device__ __forceinline__ void gemm_tf32(const float* __restrict__ A,
                                          const float* __restrict__ P,
                                          const float* __restrict__ W,
                                          const float* __restrict__ bias,
                                          float* __restrict__ Cout) {
    __shared__ float sA[2][BM * SA_STR];
    __shared__ float sB[2][BK * SB_STR];

    const int tid = threadIdx.x;
    const int lane = tid & 31;
    const int warp = tid >> 5;
    const int warp_m = warp >> 2;        // 0..1
    const int warp_n = warp & 3;         // 0..3
    const int gr = lane >> 2;            // 0..7
    const int c  = lane & 3;             // 0..3
    const int m0 = blockIdx.y * BM;
    const int n0 = blockIdx.x * BN;

    // global-load indices
    const int arow = tid >> 2, acol = (tid & 3) * 4;   // A: 64x16, float4 each
    const int brow = tid >> 4, bcol = (tid & 15) * 4;  // W: 16x64, float4 each

    float acc[2][2][4];
#pragma unroll
    for (int mt = 0; mt < 2; mt++)
#pragma unroll
        for (int nt = 0; nt < 2; nt++)
#pragma unroll
            for (int r = 0; r < 4; r++) acc[mt][nt][r] = 0.f;

    // preload tile 0
    {
        const float* ap = &A[(m0 + arow) * DIM + acol];
        float4 af = *reinterpret_cast<const float4*>(ap);
        if (P) {
            float4 pf = *reinterpret_cast<const float4*>(&P[(m0 + arow) * DIM + acol]);
            af.x += pf.x; af.y += pf.y; af.z += pf.z; af.w += pf.w;
        }
        float4 bf = *reinterpret_cast<const float4*>(&W[brow * DIM + n0 + bcol]);
        float4 at = make_float4(to_tf32(af.x), to_tf32(af.y), to_tf32(af.z), to_tf32(af.w));
        float4 bt = make_float4(to_tf32(bf.x), to_tf32(bf.y), to_tf32(bf.z), to_tf32(bf.w));
        *reinterpret_cast<float4*>(&sA[0][arow * SA_STR + acol]) = at;
        *reinterpret_cast<float4*>(&sB[0][brow * SB_STR + bcol]) = bt;
    }
    __syncthreads();

    int s = 0;
    const int NITER = DIM / BK;          // 32
    for (int it = 0; it < NITER; it++) {
        const int k0n = (it + 1) * BK;
        const bool has = (k0n < DIM);
        float4 af, bf;
        if (has) {
            af = *reinterpret_cast<const float4*>(&A[(m0 + arow) * DIM + k0n + acol]);
            if (P) {
                float4 pf = *reinterpret_cast<const float4*>(&P[(m0 + arow) * DIM + k0n + acol]);
                af.x += pf.x; af.y += pf.y; af.z += pf.z; af.w += pf.w;
            }
            bf = *reinterpret_cast<const float4*>(&W[(k0n + brow) * DIM + n0 + bcol]);
        }

        // compute on buffer s
#pragma unroll
        for (int ks = 0; ks < 2; ks++) {
            const int kb = ks * 8;
            uint32_t a[2][4];
#pragma unroll
            for (int mt = 0; mt < 2; mt++) {
                const float* ap = &sA[s][(warp_m * 32 + mt * 16 + gr) * SA_STR + kb + c];
                a[mt][0] = __float_as_uint(ap[0]);
                a[mt][1] = __float_as_uint(ap[8 * SA_STR]);
                a[mt][2] = __float_as_uint(ap[4]);
                a[mt][3] = __float_as_uint(ap[8 * SA_STR + 4]);
            }
#pragma unroll
            for (int nt = 0; nt < 2; nt++) {
                const float* bp = &sB[s][(kb + c) * SB_STR + warp_n * 16 + nt * 8 + gr];
                uint32_t b0 = __float_as_uint(bp[0]);
                uint32_t b1 = __float_as_uint(bp[4 * SB_STR]);
#pragma unroll
                for (int mt = 0; mt < 2; mt++)
                    mma_tf32(acc[mt][nt], a[mt], b0, b1);
            }
        }

        if (has) {
            float4 at = make_float4(to_tf32(af.x), to_tf32(af.y), to_tf32(af.z), to_tf32(af.w));
            float4 bt = make_float4(to_tf32(bf.x), to_tf32(bf.y), to_tf32(bf.z), to_tf32(bf.w));
            *reinterpret_cast<float4*>(&sA[s ^ 1][arow * SA_STR + acol]) = at;
            *reinterpret_cast<float4*>(&sB[s ^ 1][brow * SB_STR + bcol]) = bt;
            __syncthreads();
            s ^= 1;
        }
    }

    // epilogue: C layout m16n8 -> rows gr, gr+8; cols 2c, 2c+1
#pragma unroll
    for (int mt = 0; mt < 2; mt++) {
#pragma unroll
        for (int nt = 0; nt < 2; nt++) {
            const int col = n0 + warp_n * 16 + nt * 8 + 2 * c;
            const float b0 = bias[col], b1 = bias[col + 1];
            const int r0 = m0 + warp_m * 32 + mt * 16 + gr;
            float2 v0 = make_float2(acc[mt][nt][0] + b0, acc[mt][nt][1] + b1);
            float2 v1 = make_float2(acc[mt][nt][2] + b0, acc[mt][nt][3] + b1);
            *reinterpret_cast<float2*>(&Cout[r0 * DIM + col]) = v0;
            *reinterpret_cast<float2*>(&Cout[(r0 + 8) * DIM + col]) = v1;
        }
    }
}

__global__ void proj_qkv(const float* __restrict__ xq, const float* __restrict__ xk,
                         const float* __restrict__ pos,
                         const float* __restrict__ Wq, const float* __restrict__ bq,
                         const float* __restrict__ Wk, const float* __restrict__ bk,
                         const float* __restrict__ Wv, const float* __restrict__ bv) {
    const float *A, *P, *W, *bias;
    float* out;
    if (blockIdx.z == 0)      { A = xq; P = pos;     W = Wq; bias = bq; out = g_q; }
    else if (blockIdx.z == 1) { A = xk; P = pos;     W = Wk; bias = bk; out = g_k; }
    else                      { A = xk; P = nullptr; W = Wv; bias = bv; out = g_v; }
    gemm_tf32(A, P, W, bias, out);
}

__global__ void proj_o(const float* __restrict__ Wo, const float* __restrict__ bo,
                       float* __restrict__ out) {
    gemm_tf32(g_att, nullptr, Wo, bo, out);
}

// ---------------------------------------------------------------------------
// Attention (fp32 register-tiled flash, as R5) + float4 P-loads in PV.
// ---------------------------------------------------------------------------
#define SQT_STRIDE 60
#define SKT_STRIDE 68
#define A2_SQT (HD * SQT_STRIDE)
#define A2_SKT (HD * SKT_STRIDE)
#define A2_SV  (KT * 68)
#define A2_SP  (QT * 68)
#define A2_SMEM_FLOATS (A2_SQT + A2_SKT + A2_SV + A2_SP)
#define A2_SMEM_BYTES  (A2_SMEM_FLOATS * 4)

__global__ void attn2(const int* __restrict__ channels) {
    extern __shared__ float sm[];
    float* sQt = sm;
    float* sKt = sQt + A2_SQT;
    float* sV  = sKt + A2_SKT;
    float* sP  = sV  + A2_SV;

    const int tid = threadIdx.x;
    const int tx = tid & 15;
    const int ty = tid >> 4;
    const int h = blockIdx.y;
    const int qbase = blockIdx.x * QT;
    const bool active = (ty < 14);

    int off = 0, segs = 0, sege = 0;
#pragma unroll
    for (int i = 0; i < 4; i++) {
        int len = channels[i] * S_TOK;
        if (qbase >= off && qbase < off + len) { segs = off; sege = off + len; }
        off += len;
    }

    for (int idx = tid; idx < QT * HD; idx += 256) {
        int r = idx >> 6, d = idx & 63;
        sQt[d * SQT_STRIDE + r] = g_q[(qbase + r) * DIM + h * HD + d];
    }

    float m[4], l[4], o[4][4];
#pragma unroll
    for (int i = 0; i < 4; i++) {
        m[i] = -INFINITY; l[i] = 0.f;
#pragma unroll
        for (int j = 0; j < 4; j++) o[i][j] = 0.f;
    }

    const float scale = 0.125f;

    for (int kb = segs; kb < sege; kb += KT) {
        int valid = sege - kb; if (valid > KT) valid = KT;

        __syncthreads();
        for (int idx = tid; idx < KT * HD; idx += 256) {
            int r = idx >> 6, d = idx & 63;
            float kv = 0.f, vv = 0.f;
            if (r < valid) {
                int base = (kb + r) * DIM + h * HD + d;
                kv = g_k[base];
                vv = g_v[base];
            }
            sKt[d * SKT_STRIDE + r] = kv;
            sV [r * 68 + d] = vv;
        }
        __syncthreads();

        if (active) {
            float s[4][4];
#pragma unroll
            for (int i = 0; i < 4; i++)
#pragma unroll
                for (int j = 0; j < 4; j++) s[i][j] = 0.f;

            const float* qp = sQt + 4 * ty;
            const float* kp = sKt + 4 * tx;
#pragma unroll 8
            for (int d = 0; d < HD; d++) {
                float4 a4 = *reinterpret_cast<const float4*>(qp + d * SQT_STRIDE);
                float4 b4 = *reinterpret_cast<const float4*>(kp + d * SKT_STRIDE);
                float a[4] = {a4.x, a4.y, a4.z, a4.w};
                float b[4] = {b4.x, b4.y, b4.z, b4.w};
#pragma unroll
                for (int i = 0; i < 4; i++)
#pragma unroll
                    for (int j = 0; j < 4; j++)
                        s[i][j] += a[i] * b[j];
            }

#pragma unroll
            for (int i = 0; i < 4; i++)
#pragma unroll
                for (int j = 0; j < 4; j++) {
                    s[i][j] *= scale;
                    if (4 * tx + j >= valid) s[i][j] = -1e30f;
                }

#pragma unroll
            for (int i = 0; i < 4; i++) {
                float v = fmaxf(fmaxf(s[i][0], s[i][1]), fmaxf(s[i][2], s[i][3]));
#pragma unroll
                for (int w = 1; w < 16; w <<= 1)
                    v = fmaxf(v, __shfl_xor_sync(0xFFFFFFFFu, v, w));
                float mnew = fmaxf(m[i], v);
                float corr = __expf(m[i] - mnew);
                m[i] = mnew;
                float ps = 0.f;
#pragma unroll
                for (int j = 0; j < 4; j++) {
                    float p = __expf(s[i][j] - mnew);
                    s[i][j] = p;
                    ps += p;
                }
#pragma unroll
                for (int w = 1; w < 16; w <<= 1)
                    ps += __shfl_xor_sync(0xFFFFFFFFu, ps, w);
                l[i] = l[i] * corr + ps;
#pragma unroll
                for (int j = 0; j < 4; j++) o[i][j] *= corr;
            }

#pragma unroll
            for (int i = 0; i < 4; i++) {
                float4 p4 = make_float4(s[i][0], s[i][1], s[i][2], s[i][3]);
                *reinterpret_cast<float4*>(&sP[(4 * ty + i) * 68 + 4 * tx]) = p4;
            }
        }
        __syncthreads();

        if (active) {
            const float* vp = sV + 4 * tx;
            const float* pp = sP + (4 * ty) * 68;
#pragma unroll 2
            for (int j = 0; j < KT; j += 4) {
                float4 P0 = *reinterpret_cast<const float4*>(pp + j);
                float4 P1 = *reinterpret_cast<const float4*>(pp + 68 + j);
                float4 P2 = *reinterpret_cast<const float4*>(pp + 136 + j);
                float4 P3 = *reinterpret_cast<const float4*>(pp + 204 + j);
                float pr0[4] = {P0.x, P0.y, P0.z, P0.w};
                float pr1[4] = {P1.x, P1.y, P1.z, P1.w};
                float pr2[4] = {P2.x, P2.y, P2.z, P2.w};
                float pr3[4] = {P3.x, P3.y, P3.z, P3.w};
#pragma unroll
                for (int jj = 0; jj < 4; jj++) {
                    float4 v4 = *reinterpret_cast<const float4*>(vp + (j + jj) * 68);
                    o[0][0] += pr0[jj] * v4.x; o[0][1] += pr0[jj] * v4.y;
                    o[0][2] += pr0[jj] * v4.z; o[0][3] += pr0[jj] * v4.w;
                    o[1][0] += pr1[jj] * v4.x; o[1][1] += pr1[jj] * v4.y;
                    o[1][2] += pr1[jj] * v4.z; o[1][3] += pr1[jj] * v4.w;
                    o[2][0] += pr2[jj] * v4.x; o[2][1] += pr2[jj] * v4.y;
                    o[2][2] += pr2[jj] * v4.z; o[2][3] += pr2[jj] * v4.w;
                    o[3][0] += pr3[jj] * v4.x; o[3][1] += pr3[jj] * v4.y;
                    o[3][2] += pr3[jj] * v4.z; o[3][3] += pr3[jj] * v4.w;
                }
            }
        }
    }

    if (active) {
#pragma unroll
        for (int i = 0; i < 4; i++) {
            float inv = 1.f / l[i];
            float4 r4 = make_float4(o[i][0] * inv, o[i][1] * inv,
                                    o[i][2] * inv, o[i][3] * inv);
            *reinterpret_cast<float4*>(
                &g_att[(qbase + 4 * ty + i) * DIM + h * HD + 4 * tx]) = r4;
        }
    }
}

// ---------------------------------------------------------------------------
extern "C" void kernel_launch(void* const* d_in, const int* in_sizes, int n_in,
                              void* d_out, int out_size) {
    const float* xq  = (const float*)d_in[0];
    const float* xk  = (const float*)d_in[1];
    const float* pos = (const float*)d_in[2];
    const int*   channels = (const int*)d_in[3];
    const float* Wq = (const float*)d_in[4];  const float* bq = (const float*)d_in[5];
    const float* Wk = (const float*)d_in[6];  const float* bk = (const float*)d_in[7];
    const float* Wv = (const float*)d_in[8];  const float* bv = (const float*)d_in[9];
    const float* Wo = (const float*)d_in[10]; const float* bo = (const float*)d_in[11];

    cudaFuncSetAttribute(attn2, cudaFuncAttributeMaxDynamicSharedMemorySize,
                         A2_SMEM_BYTES);

    proj_qkv<<<dim3(DIM / BN, T_TOK / BM, 3), 256>>>(xq, xk, pos, Wq, bq, Wk, bk, Wv, bv);
    attn2<<<dim3(NTILES, NH), 256, A2_SMEM_BYTES>>>(channels);
    proj_o<<<dim3(DIM / BN, T_TOK / BM, 1), 256>>>(Wo, bo, (float*)d_out);
}

// round 9
// speedup vs baseline: 4.6708x; 1.5577x over previous
#include <cuda_runtime.h>
#include <math.h>
#include <stdint.h>

#define T_TOK 3136
#define DIM   512
#define NH    8
#define HD    64
#define S_TOK 196
#define QT    56
#define NTILES (T_TOK / QT)   // 56

// Scratch (no allocations allowed)
__device__ float g_q[T_TOK * DIM];
__device__ float g_k[T_TOK * DIM];
__device__ float g_v[T_TOK * DIM];
__device__ float g_att[T_TOK * DIM];

__device__ __forceinline__ float to_tf32(float x) {
    uint32_t u;
    asm("cvt.rna.tf32.f32 %0, %1;" : "=r"(u) : "f"(x));
    return __uint_as_float(u);
}

__device__ __forceinline__ void mma_tf32(float* d, const uint32_t* a,
                                         uint32_t b0, uint32_t b1) {
    asm volatile(
        "mma.sync.aligned.m16n8k8.row.col.f32.tf32.tf32.f32 "
        "{%0,%1,%2,%3}, {%4,%5,%6,%7}, {%8,%9}, {%0,%1,%2,%3};\n"
        : "+f"(d[0]), "+f"(d[1]), "+f"(d[2]), "+f"(d[3])
        : "r"(a[0]), "r"(a[1]), "r"(a[2]), "r"(a[3]), "r"(b0), "r"(b1));
}

// ---------------------------------------------------------------------------
// TF32 tensor-core GEMM (unchanged from R8): C = (A(+P)) @ W + bias
// ---------------------------------------------------------------------------
#define BM 64
#define BN 64
#define BK 16
#define SA_STR 20
#define SB_STR 72

__device__ __forceinline__ void gemm_tf32(const float* __restrict__ A,
                                          const float* __restrict__ P,
                                          const float* __restrict__ W,
                                          const float* __restrict__ bias,
                                          float* __restrict__ Cout) {
    __shared__ float sA[2][BM * SA_STR];
    __shared__ float sB[2][BK * SB_STR];

    const int tid = threadIdx.x;
    const int lane = tid & 31;
    const int warp = tid >> 5;
    const int warp_m = warp >> 2;
    const int warp_n = warp & 3;
    const int gr = lane >> 2;
    const int c  = lane & 3;
    const int m0 = blockIdx.y * BM;
    const int n0 = blockIdx.x * BN;

    const int arow = tid >> 2, acol = (tid & 3) * 4;
    const int brow = tid >> 4, bcol = (tid & 15) * 4;

    float acc[2][2][4];
#pragma unroll
    for (int mt = 0; mt < 2; mt++)
#pragma unroll
        for (int nt = 0; nt < 2; nt++)
#pragma unroll
            for (int r = 0; r < 4; r++) acc[mt][nt][r] = 0.f;

    {
        float4 af = *reinterpret_cast<const float4*>(&A[(m0 + arow) * DIM + acol]);
        if (P) {
            float4 pf = *reinterpret_cast<const float4*>(&P[(m0 + arow) * DIM + acol]);
            af.x += pf.x; af.y += pf.y; af.z += pf.z; af.w += pf.w;
        }
        float4 bf = *reinterpret_cast<const float4*>(&W[brow * DIM + n0 + bcol]);
        float4 at = make_float4(to_tf32(af.x), to_tf32(af.y), to_tf32(af.z), to_tf32(af.w));
        float4 bt = make_float4(to_tf32(bf.x), to_tf32(bf.y), to_tf32(bf.z), to_tf32(bf.w));
        *reinterpret_cast<float4*>(&sA[0][arow * SA_STR + acol]) = at;
        *reinterpret_cast<float4*>(&sB[0][brow * SB_STR + bcol]) = bt;
    }
    __syncthreads();

    int s = 0;
    const int NITER = DIM / BK;
    for (int it = 0; it < NITER; it++) {
        const int k0n = (it + 1) * BK;
        const bool has = (k0n < DIM);
        float4 af, bf;
        if (has) {
            af = *reinterpret_cast<const float4*>(&A[(m0 + arow) * DIM + k0n + acol]);
            if (P) {
                float4 pf = *reinterpret_cast<const float4*>(&P[(m0 + arow) * DIM + k0n + acol]);
                af.x += pf.x; af.y += pf.y; af.z += pf.z; af.w += pf.w;
            }
            bf = *reinterpret_cast<const float4*>(&W[(k0n + brow) * DIM + n0 + bcol]);
        }

#pragma unroll
        for (int ks = 0; ks < 2; ks++) {
            const int kb = ks * 8;
            uint32_t a[2][4];
#pragma unroll
            for (int mt = 0; mt < 2; mt++) {
                const float* ap = &sA[s][(warp_m * 32 + mt * 16 + gr) * SA_STR + kb + c];
                a[mt][0] = __float_as_uint(ap[0]);
                a[mt][1] = __float_as_uint(ap[8 * SA_STR]);
                a[mt][2] = __float_as_uint(ap[4]);
                a[mt][3] = __float_as_uint(ap[8 * SA_STR + 4]);
            }
#pragma unroll
            for (int nt = 0; nt < 2; nt++) {
                const float* bp = &sB[s][(kb + c) * SB_STR + warp_n * 16 + nt * 8 + gr];
                uint32_t b0 = __float_as_uint(bp[0]);
                uint32_t b1 = __float_as_uint(bp[4 * SB_STR]);
#pragma unroll
                for (int mt = 0; mt < 2; mt++)
                    mma_tf32(acc[mt][nt], a[mt], b0, b1);
            }
        }

        if (has) {
            float4 at = make_float4(to_tf32(af.x), to_tf32(af.y), to_tf32(af.z), to_tf32(af.w));
            float4 bt = make_float4(to_tf32(bf.x), to_tf32(bf.y), to_tf32(bf.z), to_tf32(bf.w));
            *reinterpret_cast<float4*>(&sA[s ^ 1][arow * SA_STR + acol]) = at;
            *reinterpret_cast<float4*>(&sB[s ^ 1][brow * SB_STR + bcol]) = bt;
            __syncthreads();
            s ^= 1;
        }
    }

#pragma unroll
    for (int mt = 0; mt < 2; mt++) {
#pragma unroll
        for (int nt = 0; nt < 2; nt++) {
            const int col = n0 + warp_n * 16 + nt * 8 + 2 * c;
            const float b0 = bias[col], b1 = bias[col + 1];
            const int r0 = m0 + warp_m * 32 + mt * 16 + gr;
            float2 v0 = make_float2(acc[mt][nt][0] + b0, acc[mt][nt][1] + b1);
            float2 v1 = make_float2(acc[mt][nt][2] + b0, acc[mt][nt][3] + b1);
            *reinterpret_cast<float2*>(&Cout[r0 * DIM + col]) = v0;
            *reinterpret_cast<float2*>(&Cout[(r0 + 8) * DIM + col]) = v1;
        }
    }
}

__global__ void proj_qkv(const float* __restrict__ xq, const float* __restrict__ xk,
                         const float* __restrict__ pos,
                         const float* __restrict__ Wq, const float* __restrict__ bq,
                         const float* __restrict__ Wk, const float* __restrict__ bk,
                         const float* __restrict__ Wv, const float* __restrict__ bv) {
    const float *A, *P, *W, *bias;
    float* out;
    if (blockIdx.z == 0)      { A = xq; P = pos;     W = Wq; bias = bq; out = g_q; }
    else if (blockIdx.z == 1) { A = xk; P = pos;     W = Wk; bias = bk; out = g_k; }
    else                      { A = xk; P = nullptr; W = Wv; bias = bv; out = g_v; }
    gemm_tf32(A, P, W, bias, out);
}

__global__ void proj_o(const float* __restrict__ Wo, const float* __restrict__ bo,
                       float* __restrict__ out) {
    gemm_tf32(g_att, nullptr, Wo, bo, out);
}

// ---------------------------------------------------------------------------
// Attention v3: TF32 mma flash attention.
// Block = (56-query tile padded to M=64, head). 128 threads = 4 warps,
// warp w owns rows 16w..16w+15 and ALL 64 keys of each k-tile -> softmax is
// warp-local (quad shfl only). Q A-frags hoisted to registers. P round-trips
// through a warp-private smem region (reuses dead sQ) with __syncwarp only.
//   sQ/sP [q][key or d] stride 68  (A-frag reads: bank 4gr+c, bijective)
//   sKt   [d][key]      stride 72  (B-frag reads: bank 8c+gr, bijective)
//   sV    [key][d]      stride 72
// ---------------------------------------------------------------------------
#define SQ_STR  68
#define SKT_STR 72
#define SV_STR  72
#define A3_SMEM_FLOATS (64 * SQ_STR + 64 * SKT_STR + 64 * SV_STR)
#define A3_SMEM_BYTES  (A3_SMEM_FLOATS * 4)   // 54272

__global__ void attn3(const int* __restrict__ channels) {
    extern __shared__ float sm[];
    float* sQ  = sm;                    // 64 x 68 (reused as sP after Q-frag hoist)
    float* sKt = sQ + 64 * SQ_STR;      // 64 x 72
    float* sV  = sKt + 64 * SKT_STR;    // 64 x 72
    float* sP  = sQ;

    const int tid  = threadIdx.x;
    const int lane = tid & 31;
    const int warp = tid >> 5;
    const int gr = lane >> 2;
    const int c  = lane & 3;
    const int h = blockIdx.y;
    const int qbase = blockIdx.x * QT;

    // segment bounds for this query tile
    int off = 0, segs = 0, sege = 0;
#pragma unroll
    for (int i = 0; i < 4; i++) {
        int len = channels[i] * S_TOK;
        if (qbase >= off && qbase < off + len) { segs = off; sege = off + len; }
        off += len;
    }

    // Load Q tile (rows >= 56 zero-padded), tf32-rounded
    for (int idx = tid; idx < 64 * HD; idx += 128) {
        int r = idx >> 6, d = idx & 63;
        float v = (r < QT) ? g_q[(qbase + r) * DIM + h * HD + d] : 0.f;
        sQ[r * SQ_STR + d] = to_tf32(v);
    }
    __syncthreads();

    // Hoist Q A-frags (constant across k-tiles)
    uint32_t qf[8][4];
#pragma unroll
    for (int ks = 0; ks < 8; ks++) {
        const float* ap = &sQ[(warp * 16 + gr) * SQ_STR + ks * 8 + c];
        qf[ks][0] = __float_as_uint(ap[0]);
        qf[ks][1] = __float_as_uint(ap[8 * SQ_STR]);
        qf[ks][2] = __float_as_uint(ap[4]);
        qf[ks][3] = __float_as_uint(ap[8 * SQ_STR + 4]);
    }

    float m0 = -INFINITY, m1 = -INFINITY, l0 = 0.f, l1 = 0.f;
    float o[8][4];
#pragma unroll
    for (int nt = 0; nt < 8; nt++)
#pragma unroll
        for (int j = 0; j < 4; j++) o[nt][j] = 0.f;

    const float scale = 0.125f;

    for (int kb = segs; kb < sege; kb += 64) {
        int valid = sege - kb; if (valid > 64) valid = 64;

        __syncthreads();   // prior PV reads of sV/sP done; Q-frag hoist done (iter 0)
        for (int idx = tid; idx < 64 * HD; idx += 128) {
            int r = idx >> 6, d = idx & 63;
            float kv = 0.f, vv = 0.f;
            if (r < valid) {
                int base = (kb + r) * DIM + h * HD + d;
                kv = g_k[base];
                vv = g_v[base];
            }
            sKt[d * SKT_STR + r] = to_tf32(kv);   // transposed store (8-way, once/tile)
            sV [r * SV_STR + d]  = to_tf32(vv);
        }
        __syncthreads();

        // ---- S = Q K^T : 8 n-tiles x 8 k-steps of m16n8k8 ----
        float sfr[8][4];
#pragma unroll
        for (int nt = 0; nt < 8; nt++)
#pragma unroll
            for (int j = 0; j < 4; j++) sfr[nt][j] = 0.f;

#pragma unroll
        for (int nt = 0; nt < 8; nt++) {
#pragma unroll
            for (int ks = 0; ks < 8; ks++) {
                const float* bp = &sKt[(ks * 8 + c) * SKT_STR + nt * 8 + gr];
                uint32_t b0 = __float_as_uint(bp[0]);
                uint32_t b1 = __float_as_uint(bp[4 * SKT_STR]);
                mma_tf32(sfr[nt], qf[ks], b0, b1);
            }
        }

        // ---- scale + mask + warp-local online softmax (fp32) ----
        float tmax0 = -INFINITY, tmax1 = -INFINITY;
#pragma unroll
        for (int nt = 0; nt < 8; nt++) {
            int col = nt * 8 + 2 * c;
            float s0 = sfr[nt][0] * scale, s1 = sfr[nt][1] * scale;
            float s2 = sfr[nt][2] * scale, s3 = sfr[nt][3] * scale;
            if (col     >= valid) { s0 = -1e30f; s2 = -1e30f; }
            if (col + 1 >= valid) { s1 = -1e30f; s3 = -1e30f; }
            sfr[nt][0] = s0; sfr[nt][1] = s1; sfr[nt][2] = s2; sfr[nt][3] = s3;
            tmax0 = fmaxf(tmax0, fmaxf(s0, s1));
            tmax1 = fmaxf(tmax1, fmaxf(s2, s3));
        }
        tmax0 = fmaxf(tmax0, __shfl_xor_sync(0xFFFFFFFFu, tmax0, 1));
        tmax0 = fmaxf(tmax0, __shfl_xor_sync(0xFFFFFFFFu, tmax0, 2));
        tmax1 = fmaxf(tmax1, __shfl_xor_sync(0xFFFFFFFFu, tmax1, 1));
        tmax1 = fmaxf(tmax1, __shfl_xor_sync(0xFFFFFFFFu, tmax1, 2));

        float mn0 = fmaxf(m0, tmax0), mn1 = fmaxf(m1, tmax1);
        float corr0 = __expf(m0 - mn0), corr1 = __expf(m1 - mn1);
        m0 = mn0; m1 = mn1;

        float ps0 = 0.f, ps1 = 0.f;
#pragma unroll
        for (int nt = 0; nt < 8; nt++) {
            float p0 = __expf(sfr[nt][0] - mn0);
            float p1 = __expf(sfr[nt][1] - mn0);
            float p2 = __expf(sfr[nt][2] - mn1);
            float p3 = __expf(sfr[nt][3] - mn1);
            sfr[nt][0] = p0; sfr[nt][1] = p1; sfr[nt][2] = p2; sfr[nt][3] = p3;
            ps0 += p0 + p1; ps1 += p2 + p3;
        }
        ps0 += __shfl_xor_sync(0xFFFFFFFFu, ps0, 1);
        ps0 += __shfl_xor_sync(0xFFFFFFFFu, ps0, 2);
        ps1 += __shfl_xor_sync(0xFFFFFFFFu, ps1, 1);
        ps1 += __shfl_xor_sync(0xFFFFFFFFu, ps1, 2);
        l0 = l0 * corr0 + ps0;
        l1 = l1 * corr1 + ps1;

#pragma unroll
        for (int nt = 0; nt < 8; nt++) {
            o[nt][0] *= corr0; o[nt][1] *= corr0;
            o[nt][2] *= corr1; o[nt][3] *= corr1;
        }

        // ---- spill P (tf32) to warp-private smem, remap C-frag -> A-frag ----
        {
            float* pr0 = &sP[(warp * 16 + gr) * SQ_STR];
            float* pr1 = &sP[(warp * 16 + gr + 8) * SQ_STR];
#pragma unroll
            for (int nt = 0; nt < 8; nt++) {
                int col = nt * 8 + 2 * c;
                *reinterpret_cast<float2*>(pr0 + col) =
                    make_float2(to_tf32(sfr[nt][0]), to_tf32(sfr[nt][1]));
                *reinterpret_cast<float2*>(pr1 + col) =
                    make_float2(to_tf32(sfr[nt][2]), to_tf32(sfr[nt][3]));
            }
        }
        __syncwarp();

        // ---- O += P V : k-dim = keys ----
#pragma unroll
        for (int ks = 0; ks < 8; ks++) {
            const float* ap = &sP[(warp * 16 + gr) * SQ_STR + ks * 8 + c];
            uint32_t a[4];
            a[0] = __float_as_uint(ap[0]);
            a[1] = __float_as_uint(ap[8 * SQ_STR]);
            a[2] = __float_as_uint(ap[4]);
            a[3] = __float_as_uint(ap[8 * SQ_STR + 4]);
#pragma unroll
            for (int nt = 0; nt < 8; nt++) {
                const float* bp = &sV[(ks * 8 + c) * SV_STR + nt * 8 + gr];
                uint32_t b0 = __float_as_uint(bp[0]);
                uint32_t b1 = __float_as_uint(bp[4 * SV_STR]);
                mma_tf32(o[nt], a, b0, b1);
            }
        }
    }

    // ---- epilogue ----
    const int lr0 = warp * 16 + gr;
    const float inv0 = 1.f / l0, inv1 = 1.f / l1;
#pragma unroll
    for (int nt = 0; nt < 8; nt++) {
        int col = h * HD + nt * 8 + 2 * c;
        if (lr0 < QT)
            *reinterpret_cast<float2*>(&g_att[(qbase + lr0) * DIM + col]) =
                make_float2(o[nt][0] * inv0, o[nt][1] * inv0);
        if (lr0 + 8 < QT)
            *reinterpret_cast<float2*>(&g_att[(qbase + lr0 + 8) * DIM + col]) =
                make_float2(o[nt][2] * inv1, o[nt][3] * inv1);
    }
}

// ---------------------------------------------------------------------------
extern "C" void kernel_launch(void* const* d_in, const int* in_sizes, int n_in,
                              void* d_out, int out_size) {
    const float* xq  = (const float*)d_in[0];
    const float* xk  = (const float*)d_in[1];
    const float* pos = (const float*)d_in[2];
    const int*   channels = (const int*)d_in[3];
    const float* Wq = (const float*)d_in[4];  const float* bq = (const float*)d_in[5];
    const float* Wk = (const float*)d_in[6];  const float* bk = (const float*)d_in[7];
    const float* Wv = (const float*)d_in[8];  const float* bv = (const float*)d_in[9];
    const float* Wo = (const float*)d_in[10]; const float* bo = (const float*)d_in[11];

    cudaFuncSetAttribute(attn3, cudaFuncAttributeMaxDynamicSharedMemorySize,
                         A3_SMEM_BYTES);

    proj_qkv<<<dim3(DIM / BN, T_TOK / BM, 3), 256>>>(xq, xk, pos, Wq, bq, Wk, bk, Wv, bv);
    attn3<<<dim3(NTILES, NH), 128, A3_SMEM_BYTES>>>(channels);
    proj_o<<<dim3(DIM / BN, T_TOK / BM, 1), 256>>>(Wo, bo, (float*)d_out);
}

// round 10
// speedup vs baseline: 6.1052x; 1.3071x over previous
#include <cuda_runtime.h>
#include <math.h>
#include <stdint.h>

#define T_TOK 3136
#define DIM   512
#define NH    8
#define HD    64
#define S_TOK 196
#define QT    56
#define NTILES (T_TOK / QT)   // 56

// Scratch (no allocations allowed)
__device__ float g_q[T_TOK * DIM];
__device__ float g_k[T_TOK * DIM];
__device__ float g_v[T_TOK * DIM];
__device__ float g_att[T_TOK * DIM];

__device__ __forceinline__ float to_tf32(float x) {
    uint32_t u;
    asm("cvt.rna.tf32.f32 %0, %1;" : "=r"(u) : "f"(x));
    return __uint_as_float(u);
}

__device__ __forceinline__ void mma_tf32(float* d, const uint32_t* a,
                                         uint32_t b0, uint32_t b1) {
    asm volatile(
        "mma.sync.aligned.m16n8k8.row.col.f32.tf32.tf32.f32 "
        "{%0,%1,%2,%3}, {%4,%5,%6,%7}, {%8,%9}, {%0,%1,%2,%3};\n"
        : "+f"(d[0]), "+f"(d[1]), "+f"(d[2]), "+f"(d[3])
        : "r"(a[0]), "r"(a[1]), "r"(a[2]), "r"(a[3]), "r"(b0), "r"(b1));
}

// ---------------------------------------------------------------------------
// TF32 GEMM v2: C[3136,512] = (A(+P)) @ W + bias
// BM=BN=128, BK=16, 256 threads (8 warps, 2x4), warp tile 64x32 (MT=4,NT=4).
// LDS:mma = 1.5 per k-step. Double-buffered. M-tail: clamped loads, guarded
// stores (3136 = 24*128 + 64).
// ---------------------------------------------------------------------------
#define BM 128
#define BN 128
#define BK 16
#define SA_STR 20
#define SB_STR 136

__device__ __forceinline__ void gemm_tf32(const float* __restrict__ A,
                                          const float* __restrict__ P,
                                          const float* __restrict__ W,
                                          const float* __restrict__ bias,
                                          float* __restrict__ Cout) {
    __shared__ float sA[2][BM * SA_STR];
    __shared__ float sB[2][BK * SB_STR];

    const int tid = threadIdx.x;
    const int lane = tid & 31;
    const int warp = tid >> 5;
    const int warp_m = warp >> 2;        // 0..1 (64 rows each)
    const int warp_n = warp & 3;         // 0..3 (32 cols each)
    const int gr = lane >> 2;            // 0..7
    const int c  = lane & 3;             // 0..3
    const int m0 = blockIdx.y * BM;
    const int n0 = blockIdx.x * BN;

    const int arow = tid >> 2, acol = (tid & 3) * 4;   // + it2*64 rows
    const int brow = tid >> 5, bcol = (tid & 31) * 4;  // + it2*8 rows

    float acc[4][4][4];
#pragma unroll
    for (int mt = 0; mt < 4; mt++)
#pragma unroll
        for (int nt = 0; nt < 4; nt++)
#pragma unroll
            for (int r = 0; r < 4; r++) acc[mt][nt][r] = 0.f;

    // load tile k0 into buffer 0
#pragma unroll
    for (int it2 = 0; it2 < 2; it2++) {
        int grow = m0 + arow + it2 * 64;
        if (grow > T_TOK - 1) grow = T_TOK - 1;
        float4 af = *reinterpret_cast<const float4*>(&A[grow * DIM + acol]);
        if (P) {
            float4 pf = *reinterpret_cast<const float4*>(&P[grow * DIM + acol]);
            af.x += pf.x; af.y += pf.y; af.z += pf.z; af.w += pf.w;
        }
        float4 at = make_float4(to_tf32(af.x), to_tf32(af.y), to_tf32(af.z), to_tf32(af.w));
        *reinterpret_cast<float4*>(&sA[0][(arow + it2 * 64) * SA_STR + acol]) = at;

        float4 bf = *reinterpret_cast<const float4*>(&W[(brow + it2 * 8) * DIM + n0 + bcol]);
        float4 bt = make_float4(to_tf32(bf.x), to_tf32(bf.y), to_tf32(bf.z), to_tf32(bf.w));
        *reinterpret_cast<float4*>(&sB[0][(brow + it2 * 8) * SB_STR + bcol]) = bt;
    }
    __syncthreads();

    int s = 0;
    const int NITER = DIM / BK;          // 32
    for (int it = 0; it < NITER; it++) {
        const int k0n = (it + 1) * BK;
        const bool has = (k0n < DIM);
        float4 af[2], bf[2];
        if (has) {
#pragma unroll
            for (int it2 = 0; it2 < 2; it2++) {
                int grow = m0 + arow + it2 * 64;
                if (grow > T_TOK - 1) grow = T_TOK - 1;
                af[it2] = *reinterpret_cast<const float4*>(&A[grow * DIM + k0n + acol]);
                if (P) {
                    float4 pf = *reinterpret_cast<const float4*>(&P[grow * DIM + k0n + acol]);
                    af[it2].x += pf.x; af[it2].y += pf.y;
                    af[it2].z += pf.z; af[it2].w += pf.w;
                }
                bf[it2] = *reinterpret_cast<const float4*>(
                    &W[(k0n + brow + it2 * 8) * DIM + n0 + bcol]);
            }
        }

#pragma unroll
        for (int ks = 0; ks < 2; ks++) {
            const int kb = ks * 8;
            uint32_t a[4][4];
#pragma unroll
            for (int mt = 0; mt < 4; mt++) {
                const float* ap = &sA[s][(warp_m * 64 + mt * 16 + gr) * SA_STR + kb + c];
                a[mt][0] = __float_as_uint(ap[0]);
                a[mt][1] = __float_as_uint(ap[8 * SA_STR]);
                a[mt][2] = __float_as_uint(ap[4]);
                a[mt][3] = __float_as_uint(ap[8 * SA_STR + 4]);
            }
#pragma unroll
            for (int nt = 0; nt < 4; nt++) {
                const float* bp = &sB[s][(kb + c) * SB_STR + warp_n * 32 + nt * 8 + gr];
                uint32_t b0 = __float_as_uint(bp[0]);
                uint32_t b1 = __float_as_uint(bp[4 * SB_STR]);
#pragma unroll
                for (int mt = 0; mt < 4; mt++)
                    mma_tf32(acc[mt][nt], a[mt], b0, b1);
            }
        }

        if (has) {
#pragma unroll
            for (int it2 = 0; it2 < 2; it2++) {
                float4 at = make_float4(to_tf32(af[it2].x), to_tf32(af[it2].y),
                                        to_tf32(af[it2].z), to_tf32(af[it2].w));
                float4 bt = make_float4(to_tf32(bf[it2].x), to_tf32(bf[it2].y),
                                        to_tf32(bf[it2].z), to_tf32(bf[it2].w));
                *reinterpret_cast<float4*>(&sA[s ^ 1][(arow + it2 * 64) * SA_STR + acol]) = at;
                *reinterpret_cast<float4*>(&sB[s ^ 1][(brow + it2 * 8) * SB_STR + bcol]) = bt;
            }
            __syncthreads();
            s ^= 1;
        }
    }

#pragma unroll
    for (int mt = 0; mt < 4; mt++) {
#pragma unroll
        for (int nt = 0; nt < 4; nt++) {
            const int col = n0 + warp_n * 32 + nt * 8 + 2 * c;
            const float b0 = bias[col], b1 = bias[col + 1];
            const int r0 = m0 + warp_m * 64 + mt * 16 + gr;
            if (r0 < T_TOK)
                *reinterpret_cast<float2*>(&Cout[r0 * DIM + col]) =
                    make_float2(acc[mt][nt][0] + b0, acc[mt][nt][1] + b1);
            if (r0 + 8 < T_TOK)
                *reinterpret_cast<float2*>(&Cout[(r0 + 8) * DIM + col]) =
                    make_float2(acc[mt][nt][2] + b0, acc[mt][nt][3] + b1);
        }
    }
}

__global__ void proj_qkv(const float* __restrict__ xq, const float* __restrict__ xk,
                         const float* __restrict__ pos,
                         const float* __restrict__ Wq, const float* __restrict__ bq,
                         const float* __restrict__ Wk, const float* __restrict__ bk,
                         const float* __restrict__ Wv, const float* __restrict__ bv) {
    const float *A, *P, *W, *bias;
    float* out;
    if (blockIdx.z == 0)      { A = xq; P = pos;     W = Wq; bias = bq; out = g_q; }
    else if (blockIdx.z == 1) { A = xk; P = pos;     W = Wk; bias = bk; out = g_k; }
    else                      { A = xk; P = nullptr; W = Wv; bias = bv; out = g_v; }
    gemm_tf32(A, P, W, bias, out);
}

__global__ void proj_o(const float* __restrict__ Wo, const float* __restrict__ bo,
                       float* __restrict__ out) {
    gemm_tf32(g_att, nullptr, Wo, bo, out);
}

// ---------------------------------------------------------------------------
// Attention v3b: TF32 mma flash attention with vectorized loads + swizzled K.
//   sQ/sP [q][.] stride 68   (A-frag bank 4gr+c bijective; float4 STS clean)
//   sKt   [d][key'] stride 72, key' = key ^ ((d>>2)&7)
//        store: 2-way conflict (was 8); B-frag read: bank 8(c+nt)+gr^f, clean
//   sV    [key][d] stride 72 (float4 LDG + float4 STS, conflict-free)
// ---------------------------------------------------------------------------
#define SQ_STR  68
#define SKT_STR 72
#define SV_STR  72
#define A3_SMEM_FLOATS (64 * SQ_STR + 64 * SKT_STR + 64 * SV_STR)
#define A3_SMEM_BYTES  (A3_SMEM_FLOATS * 4)   // 54272

__global__ void attn3(const int* __restrict__ channels) {
    extern __shared__ float sm[];
    float* sQ  = sm;                    // 64 x 68 (reused as sP)
    float* sKt = sQ + 64 * SQ_STR;      // 64 x 72 (swizzled keys)
    float* sV  = sKt + 64 * SKT_STR;    // 64 x 72
    float* sP  = sQ;

    const int tid  = threadIdx.x;
    const int lane = tid & 31;
    const int warp = tid >> 5;
    const int gr = lane >> 2;
    const int c  = lane & 3;
    const int h = blockIdx.y;
    const int qbase = blockIdx.x * QT;

    int off = 0, segs = 0, sege = 0;
#pragma unroll
    for (int i = 0; i < 4; i++) {
        int len = channels[i] * S_TOK;
        if (qbase >= off && qbase < off + len) { segs = off; sege = off + len; }
        off += len;
    }

    // Q tile: float4 loads, rows >= 56 zero-padded
#pragma unroll
    for (int i = tid; i < 64 * 16; i += 128) {
        int r = i >> 4, d = (i & 15) * 4;
        float4 v = make_float4(0.f, 0.f, 0.f, 0.f);
        if (r < QT)
            v = *reinterpret_cast<const float4*>(&g_q[(qbase + r) * DIM + h * HD + d]);
        *reinterpret_cast<float4*>(&sQ[r * SQ_STR + d]) =
            make_float4(to_tf32(v.x), to_tf32(v.y), to_tf32(v.z), to_tf32(v.w));
    }
    __syncthreads();

    // Hoist Q A-frags
    uint32_t qf[8][4];
#pragma unroll
    for (int ks = 0; ks < 8; ks++) {
        const float* ap = &sQ[(warp * 16 + gr) * SQ_STR + ks * 8 + c];
        qf[ks][0] = __float_as_uint(ap[0]);
        qf[ks][1] = __float_as_uint(ap[8 * SQ_STR]);
        qf[ks][2] = __float_as_uint(ap[4]);
        qf[ks][3] = __float_as_uint(ap[8 * SQ_STR + 4]);
    }

    float m0 = -INFINITY, m1 = -INFINITY, l0 = 0.f, l1 = 0.f;
    float o[8][4];
#pragma unroll
    for (int nt = 0; nt < 8; nt++)
#pragma unroll
        for (int j = 0; j < 4; j++) o[nt][j] = 0.f;

    const float scale = 0.125f;

    for (int kb = segs; kb < sege; kb += 64) {
        int valid = sege - kb; if (valid > 64) valid = 64;

        __syncthreads();   // prior PV reads done; Q-frag hoist done (iter 0)
#pragma unroll
        for (int i = tid; i < 64 * 16; i += 128) {
            int r = i >> 4, c4 = i & 15, d = c4 * 4;
            float4 kv = make_float4(0.f, 0.f, 0.f, 0.f);
            float4 vv = make_float4(0.f, 0.f, 0.f, 0.f);
            if (r < valid) {
                int base = (kb + r) * DIM + h * HD + d;
                kv = *reinterpret_cast<const float4*>(&g_k[base]);
                vv = *reinterpret_cast<const float4*>(&g_v[base]);
            }
            // K transposed + swizzled: all 4 d-values share f = c4 & 7
            int rs = r ^ (c4 & 7);
            sKt[(d + 0) * SKT_STR + rs] = to_tf32(kv.x);
            sKt[(d + 1) * SKT_STR + rs] = to_tf32(kv.y);
            sKt[(d + 2) * SKT_STR + rs] = to_tf32(kv.z);
            sKt[(d + 3) * SKT_STR + rs] = to_tf32(kv.w);
            *reinterpret_cast<float4*>(&sV[r * SV_STR + d]) =
                make_float4(to_tf32(vv.x), to_tf32(vv.y), to_tf32(vv.z), to_tf32(vv.w));
        }
        __syncthreads();

        // ---- S = Q K^T ----
        float sfr[8][4];
#pragma unroll
        for (int nt = 0; nt < 8; nt++)
#pragma unroll
            for (int j = 0; j < 4; j++) sfr[nt][j] = 0.f;

#pragma unroll
        for (int nt = 0; nt < 8; nt++) {
#pragma unroll
            for (int ks = 0; ks < 8; ks++) {
                // row k = ks*8+c -> f = (2ks)&7; row k+4 -> f2 = (2ks+1)&7
                int key0 = nt * 8 + (gr ^ ((2 * ks) & 7));
                int key1 = nt * 8 + (gr ^ ((2 * ks + 1) & 7));
                uint32_t b0 = __float_as_uint(sKt[(ks * 8 + c) * SKT_STR + key0]);
                uint32_t b1 = __float_as_uint(sKt[(ks * 8 + c + 4) * SKT_STR + key1]);
                mma_tf32(sfr[nt], qf[ks], b0, b1);
            }
        }

        // ---- scale + mask + warp-local online softmax ----
        float tmax0 = -INFINITY, tmax1 = -INFINITY;
#pragma unroll
        for (int nt = 0; nt < 8; nt++) {
            int col = nt * 8 + 2 * c;
            float s0 = sfr[nt][0] * scale, s1 = sfr[nt][1] * scale;
            float s2 = sfr[nt][2] * scale, s3 = sfr[nt][3] * scale;
            if (col     >= valid) { s0 = -1e30f; s2 = -1e30f; }
            if (col + 1 >= valid) { s1 = -1e30f; s3 = -1e30f; }
            sfr[nt][0] = s0; sfr[nt][1] = s1; sfr[nt][2] = s2; sfr[nt][3] = s3;
            tmax0 = fmaxf(tmax0, fmaxf(s0, s1));
            tmax1 = fmaxf(tmax1, fmaxf(s2, s3));
        }
        tmax0 = fmaxf(tmax0, __shfl_xor_sync(0xFFFFFFFFu, tmax0, 1));
        tmax0 = fmaxf(tmax0, __shfl_xor_sync(0xFFFFFFFFu, tmax0, 2));
        tmax1 = fmaxf(tmax1, __shfl_xor_sync(0xFFFFFFFFu, tmax1, 1));
        tmax1 = fmaxf(tmax1, __shfl_xor_sync(0xFFFFFFFFu, tmax1, 2));

        float mn0 = fmaxf(m0, tmax0), mn1 = fmaxf(m1, tmax1);
        float corr0 = __expf(m0 - mn0), corr1 = __expf(m1 - mn1);
        m0 = mn0; m1 = mn1;

        float ps0 = 0.f, ps1 = 0.f;
#pragma unroll
        for (int nt = 0; nt < 8; nt++) {
            float p0 = __expf(sfr[nt][0] - mn0);
            float p1 = __expf(sfr[nt][1] - mn0);
            float p2 = __expf(sfr[nt][2] - mn1);
            float p3 = __expf(sfr[nt][3] - mn1);
            sfr[nt][0] = p0; sfr[nt][1] = p1; sfr[nt][2] = p2; sfr[nt][3] = p3;
            ps0 += p0 + p1; ps1 += p2 + p3;
        }
        ps0 += __shfl_xor_sync(0xFFFFFFFFu, ps0, 1);
        ps0 += __shfl_xor_sync(0xFFFFFFFFu, ps0, 2);
        ps1 += __shfl_xor_sync(0xFFFFFFFFu, ps1, 1);
        ps1 += __shfl_xor_sync(0xFFFFFFFFu, ps1, 2);
        l0 = l0 * corr0 + ps0;
        l1 = l1 * corr1 + ps1;

#pragma unroll
        for (int nt = 0; nt < 8; nt++) {
            o[nt][0] *= corr0; o[nt][1] *= corr0;
            o[nt][2] *= corr1; o[nt][3] *= corr1;
        }

        // ---- spill P (tf32) to warp-private smem ----
        {
            float* pr0 = &sP[(warp * 16 + gr) * SQ_STR];
            float* pr1 = &sP[(warp * 16 + gr + 8) * SQ_STR];
#pragma unroll
            for (int nt = 0; nt < 8; nt++) {
                int col = nt * 8 + 2 * c;
                *reinterpret_cast<float2*>(pr0 + col) =
                    make_float2(to_tf32(sfr[nt][0]), to_tf32(sfr[nt][1]));
                *reinterpret_cast<float2*>(pr1 + col) =
                    make_float2(to_tf32(sfr[nt][2]), to_tf32(sfr[nt][3]));
            }
        }
        __syncwarp();

        // ---- O += P V ----
#pragma unroll
        for (int ks = 0; ks < 8; ks++) {
            const float* ap = &sP[(warp * 16 + gr) * SQ_STR + ks * 8 + c];
            uint32_t a[4];
            a[0] = __float_as_uint(ap[0]);
            a[1] = __float_as_uint(ap[8 * SQ_STR]);
            a[2] = __float_as_uint(ap[4]);
            a[3] = __float_as_uint(ap[8 * SQ_STR + 4]);
#pragma unroll
            for (int nt = 0; nt < 8; nt++) {
                const float* bp = &sV[(ks * 8 + c) * SV_STR + nt * 8 + gr];
                uint32_t b0 = __float_as_uint(bp[0]);
                uint32_t b1 = __float_as_uint(bp[4 * SV_STR]);
                mma_tf32(o[nt], a, b0, b1);
            }
        }
    }

    // ---- epilogue ----
    const int lr0 = warp * 16 + gr;
    const float inv0 = 1.f / l0, inv1 = 1.f / l1;
#pragma unroll
    for (int nt = 0; nt < 8; nt++) {
        int col = h * HD + nt * 8 + 2 * c;
        if (lr0 < QT)
            *reinterpret_cast<float2*>(&g_att[(qbase + lr0) * DIM + col]) =
                make_float2(o[nt][0] * inv0, o[nt][1] * inv0);
        if (lr0 + 8 < QT)
            *reinterpret_cast<float2*>(&g_att[(qbase + lr0 + 8) * DIM + col]) =
                make_float2(o[nt][2] * inv1, o[nt][3] * inv1);
    }
}

// ---------------------------------------------------------------------------
extern "C" void kernel_launch(void* const* d_in, const int* in_sizes, int n_in,
                              void* d_out, int out_size) {
    const float* xq  = (const float*)d_in[0];
    const float* xk  = (const float*)d_in[1];
    const float* pos = (const float*)d_in[2];
    const int*   channels = (const int*)d_in[3];
    const float* Wq = (const float*)d_in[4];  const float* bq = (const float*)d_in[5];
    const float* Wk = (const float*)d_in[6];  const float* bk = (const float*)d_in[7];
    const float* Wv = (const float*)d_in[8];  const float* bv = (const float*)d_in[9];
    const float* Wo = (const float*)d_in[10]; const float* bo = (const float*)d_in[11];

    cudaFuncSetAttribute(attn3, cudaFuncAttributeMaxDynamicSharedMemorySize,
                         A3_SMEM_BYTES);

    const int gy = (T_TOK + BM - 1) / BM;   // 25
    proj_qkv<<<dim3(DIM / BN, gy, 3), 256>>>(xq, xk, pos, Wq, bq, Wk, bk, Wv, bv);
    attn3<<<dim3(NTILES, NH), 128, A3_SMEM_BYTES>>>(channels);
    proj_o<<<dim3(DIM / BN, gy, 1), 256>>>(Wo, bo, (float*)d_out);
}